// round 6
// baseline (speedup 1.0000x reference)
#include <cuda_runtime.h>
#include <math.h>

// Problem dims (fixed by the reference setup_inputs)
#define BB 4
#define LL 32
#define CC 16
#define HH 192
#define WW 192
#define HWN (HH * WW)                    // 36864
#define FLOW_ELEMS (BB * LL * 2 * HWN)   // 9,437,184
#define IMG_ELEMS  (BB * LL * CC * HWN)  // 75,497,472

// Ping-pong scratch (allocation-free rule: __device__ globals)
__device__ float g_flowsA[FLOW_ELEMS];
__device__ float g_flowsB[FLOW_ELEMS];
__device__ float g_imagesA[IMG_ELEMS];
__device__ float g_imagesB[IMG_ELEMS];

// Exact floor-mod by 2.0, value-identical to jnp.remainder(z, 2.0) in fp32:
//  - z*0.5f is exact (power-of-two scale), floorf exact, 2*q exact
//  - the single rounded subtraction z - 2q reproduces jnp's trunc-rem + sign-fix
//    rounding for every case in our range (incl. +/-0 and the z<0 rounding path).
__device__ __forceinline__ float floor_mod2(float z) {
    float q = floorf(__fmul_rn(z, 0.5f));
    return __fsub_rn(z, __fmul_rn(2.0f, q));
}

template <bool WRITE_FLOWS>
__global__ __launch_bounds__(256) void pscan_step_kernel(
    const float* __restrict__ srcF,
    const float* __restrict__ srcI,
    float* __restrict__ dstF,
    float* __restrict__ dstI,
    int step)
{
    const int p = blockIdx.x * blockDim.x + threadIdx.x;   // pixel in [0, HWN)
    const int t = blockIdx.y;                               // frame index
    const int b = blockIdx.z;                               // batch
    if (p >= HWN) return;

    const int frame   = b * LL + t;
    const float* icur = srcI + (size_t)frame * CC * HWN;
    float*       dimg = dstI + (size_t)frame * CC * HWN;

    if (t < step) {
        // passthrough (concatenate prefix)
        #pragma unroll
        for (int ch = 0; ch < CC; ch++)
            dimg[ch * HWN + p] = icur[ch * HWN + p];
        if (WRITE_FLOWS) {
            const float* fcur = srcF + (size_t)frame * 2 * HWN;
            float*       dflw = dstF + (size_t)frame * 2 * HWN;
            dflw[p]       = fcur[p];
            dflw[HWN + p] = fcur[HWN + p];
        }
        return;
    }

    const int x = p % WW;
    const int y = p / WW;

    const float* fcur = srcF + (size_t)frame * 2 * HWN;
    const float f0 = fcur[p];          // flow x-component
    const float f1 = fcur[HWN + p];    // flow y-component

    // base grid (pixel centers in [-1,1]) — separate roundings, NO fma,
    // matching XLA's (arange + 0.5) * (2/W) - 1 op-by-op.
    const float C2W = (float)(2.0 / 192.0);   // f64 constant rounded once, like jnp
    const float gx = __fsub_rn(__fmul_rn(__fadd_rn((float)x, 0.5f), C2W), 1.0f);
    const float gy = __fsub_rn(__fmul_rn(__fadd_rn((float)y, 0.5f), C2W), 1.0f);

    const float fx_u = __fadd_rn(gx, f0);
    const float fy   = __fadd_rn(gy, f1);

    // wrap_x: fx = remainder(fx + 1, 2) - 1, bit-exact floor-mod
    const float z  = __fadd_rn(fx_u, 1.0f);
    const float fx = __fsub_rn(floor_mod2(z), 1.0f);

    // grid_sample bilinear coords, align_corners=False:
    // ix = ((fx + 1) * 0.5) * W - 0.5, each op rounded separately (no fma)
    const float ix = __fsub_rn(__fmul_rn(__fmul_rn(__fadd_rn(fx, 1.0f), 0.5f), (float)WW), 0.5f);
    const float iy = __fsub_rn(__fmul_rn(__fmul_rn(__fadd_rn(fy, 1.0f), 0.5f), (float)HH), 0.5f);

    const float x0f = floorf(ix);
    const float y0f = floorf(iy);
    const float wx1 = __fsub_rn(ix, x0f);
    const float wy1 = __fsub_rn(iy, y0f);
    const float wx0 = __fsub_rn(1.0f, wx1);
    const float wy0 = __fsub_rn(1.0f, wy1);

    const int x0 = (int)x0f;
    const int y0 = (int)y0f;
    const int x1 = x0 + 1;
    const int y1 = y0 + 1;

    const bool vx0 = (x0 >= 0) & (x0 < WW);
    const bool vx1 = (x1 >= 0) & (x1 < WW);
    const bool vy0 = (y0 >= 0) & (y0 < HH);
    const bool vy1 = (y1 >= 0) & (y1 < HH);

    const int xc0 = min(max(x0, 0), WW - 1);
    const int xc1 = min(max(x1, 0), WW - 1);
    const int yc0 = min(max(y0, 0), HH - 1);
    const int yc1 = min(max(y1, 0), HH - 1);

    // weights, rounded exactly like the reference (w = wy*wx, one rounding),
    // with zeros-padding validity folded in (sign-of-zero preserved).
    const float w00 = __fmul_rn(__fmul_rn(wy0, wx0), (vy0 & vx0) ? 1.0f : 0.0f);
    const float w01 = __fmul_rn(__fmul_rn(wy0, wx1), (vy0 & vx1) ? 1.0f : 0.0f);
    const float w10 = __fmul_rn(__fmul_rn(wy1, wx0), (vy1 & vx0) ? 1.0f : 0.0f);
    const float w11 = __fmul_rn(__fmul_rn(wy1, wx1), (vy1 & vx1) ? 1.0f : 0.0f);

    const int i00 = yc0 * WW + xc0;
    const int i01 = yc0 * WW + xc1;
    const int i10 = yc1 * WW + xc0;
    const int i11 = yc1 * WW + xc1;

    const int prev = b * LL + (t - step);

    if (WRITE_FLOWS) {
        const float* fprev = srcF + (size_t)prev * 2 * HWN;
        float*       dflw  = dstF + (size_t)frame * 2 * HWN;
        #pragma unroll
        for (int ch = 0; ch < 2; ch++) {
            const float* plane = fprev + ch * HWN;
            // ((p00 + p01) + p10) + p11, left-assoc like the reference, no fma
            float s = __fadd_rn(
                        __fadd_rn(
                          __fadd_rn(__fmul_rn(plane[i00], w00),
                                    __fmul_rn(plane[i01], w01)),
                          __fmul_rn(plane[i10], w10)),
                        __fmul_rn(plane[i11], w11));
            dflw[ch * HWN + p] = __fadd_rn((ch == 0 ? f0 : f1), s);
        }
    }

    const float* iprev = srcI + (size_t)prev * CC * HWN;
    #pragma unroll
    for (int ch = 0; ch < CC; ch++) {
        const float* plane = iprev + ch * HWN;
        float s = __fadd_rn(
                    __fadd_rn(
                      __fadd_rn(__fmul_rn(plane[i00], w00),
                                __fmul_rn(plane[i01], w01)),
                      __fmul_rn(plane[i10], w10)),
                    __fmul_rn(plane[i11], w11));
        dimg[ch * HWN + p] = __fadd_rn(icur[ch * HWN + p], s);
    }
}

extern "C" void kernel_launch(void* const* d_in, const int* in_sizes, int n_in,
                              void* d_out, int out_size)
{
    // Defensive input-order resolution via element counts
    const float* in_flows  = (const float*)d_in[0];  // [B,L,2,H,W]
    const float* in_images = (const float*)d_in[1];  // [B,L,C,H,W]
    if (in_sizes[0] == IMG_ELEMS && in_sizes[1] == FLOW_ELEMS) {
        in_flows  = (const float*)d_in[1];
        in_images = (const float*)d_in[0];
    }
    float* out_images = (float*)d_out;               // [B,L,C,H,W]

    float *fA, *fB, *iA, *iB;
    cudaGetSymbolAddress((void**)&fA, g_flowsA);
    cudaGetSymbolAddress((void**)&fB, g_flowsB);
    cudaGetSymbolAddress((void**)&iA, g_imagesA);
    cudaGetSymbolAddress((void**)&iB, g_imagesB);

    dim3 block(256);
    dim3 grid(HWN / 256, LL, BB);   // 144 x 32 x 4

    // step 1: inputs -> A
    pscan_step_kernel<true><<<grid, block>>>(in_flows, in_images, fA, iA, 1);
    // step 2: A -> B
    pscan_step_kernel<true><<<grid, block>>>(fA, iA, fB, iB, 2);
    // step 4: B -> A
    pscan_step_kernel<true><<<grid, block>>>(fB, iB, fA, iA, 4);
    // step 8: A -> B
    pscan_step_kernel<true><<<grid, block>>>(fA, iA, fB, iB, 8);
    // step 16: B -> d_out (images only; flows are dead)
    pscan_step_kernel<false><<<grid, block>>>(fB, iB, nullptr, out_images, 16);
}

// round 7
// speedup vs baseline: 2.4359x; 2.4359x over previous
#include <cuda_runtime.h>
#include <math.h>

// Problem dims (fixed by the reference setup_inputs)
#define BB 4
#define LL 32
#define CC 16
#define HH 192
#define WW 192
#define HWN (HH * WW)                    // 36864
#define FLOW_ELEMS (BB * LL * 2 * HWN)   // 9,437,184
#define IMG_ELEMS  (BB * LL * CC * HWN)  // 75,497,472

// Scratch (allocation-free rule: __device__ globals).
// Images in NHWC ([frame][px][16ch]) as float4 quads; flows interleaved ([frame][px][2]).
__device__ float4 g_imgA[IMG_ELEMS / 4];
__device__ float4 g_imgB[IMG_ELEMS / 4];
__device__ float2 g_flwT[FLOW_ELEMS / 2];
__device__ float2 g_flwA[FLOW_ELEMS / 2];
__device__ float2 g_flwB[FLOW_ELEMS / 2];

// Exact floor-mod by 2.0, value-identical to jnp.remainder(z, 2.0) in fp32.
__device__ __forceinline__ float floor_mod2(float z) {
    float q = floorf(__fmul_rn(z, 0.5f));
    return __fsub_rn(z, __fmul_rn(2.0f, q));
}

// Shared coordinate/weight computation (bit-exact, no fma).
struct Taps {
    int i00, i01, i10, i11;
    float w00, w01, w10, w11;
};
__device__ __forceinline__ Taps make_taps(int x, int y, float f0, float f1) {
    const float C2W = (float)(2.0 / 192.0);
    const float gx = __fsub_rn(__fmul_rn(__fadd_rn((float)x, 0.5f), C2W), 1.0f);
    const float gy = __fsub_rn(__fmul_rn(__fadd_rn((float)y, 0.5f), C2W), 1.0f);

    const float fx_u = __fadd_rn(gx, f0);
    const float fy   = __fadd_rn(gy, f1);
    const float z  = __fadd_rn(fx_u, 1.0f);
    const float fx = __fsub_rn(floor_mod2(z), 1.0f);

    const float ix = __fsub_rn(__fmul_rn(__fmul_rn(__fadd_rn(fx, 1.0f), 0.5f), (float)WW), 0.5f);
    const float iy = __fsub_rn(__fmul_rn(__fmul_rn(__fadd_rn(fy, 1.0f), 0.5f), (float)HH), 0.5f);

    const float x0f = floorf(ix);
    const float y0f = floorf(iy);
    const float wx1 = __fsub_rn(ix, x0f);
    const float wy1 = __fsub_rn(iy, y0f);
    const float wx0 = __fsub_rn(1.0f, wx1);
    const float wy0 = __fsub_rn(1.0f, wy1);

    const int x0 = (int)x0f, y0 = (int)y0f;
    const int x1 = x0 + 1,  y1 = y0 + 1;

    const bool vx0 = (x0 >= 0) & (x0 < WW);
    const bool vx1 = (x1 >= 0) & (x1 < WW);
    const bool vy0 = (y0 >= 0) & (y0 < HH);
    const bool vy1 = (y1 >= 0) & (y1 < HH);

    const int xc0 = min(max(x0, 0), WW - 1);
    const int xc1 = min(max(x1, 0), WW - 1);
    const int yc0 = min(max(y0, 0), HH - 1);
    const int yc1 = min(max(y1, 0), HH - 1);

    Taps tp;
    tp.w00 = __fmul_rn(__fmul_rn(wy0, wx0), (vy0 & vx0) ? 1.0f : 0.0f);
    tp.w01 = __fmul_rn(__fmul_rn(wy0, wx1), (vy0 & vx1) ? 1.0f : 0.0f);
    tp.w10 = __fmul_rn(__fmul_rn(wy1, wx0), (vy1 & vx0) ? 1.0f : 0.0f);
    tp.w11 = __fmul_rn(__fmul_rn(wy1, wx1), (vy1 & vx1) ? 1.0f : 0.0f);
    tp.i00 = yc0 * WW + xc0;
    tp.i01 = yc0 * WW + xc1;
    tp.i10 = yc1 * WW + xc0;
    tp.i11 = yc1 * WW + xc1;
    return tp;
}

// Exact left-assoc weighted sum: ((w00*a + w01*b) + w10*c) + w11*d
__device__ __forceinline__ float wsum(float w00, float a, float w01, float b,
                                      float w10, float c, float w11, float d) {
    return __fadd_rn(
             __fadd_rn(
               __fadd_rn(__fmul_rn(w00, a), __fmul_rn(w01, b)),
               __fmul_rn(w10, c)),
             __fmul_rn(w11, d));
}

// ---------------- transpose kernels ----------------

// images NCHW -> NHWC (float4 quads). thread = one output float4.
__global__ __launch_bounds__(256) void transpose_img_kernel(
    const float* __restrict__ src, float4* __restrict__ dst)
{
    const int idx = blockIdx.x * blockDim.x + threadIdx.x;  // [0, HWN*4)
    const int frame = blockIdx.y + blockIdx.z * LL;
    const int px = idx >> 2;
    const int cq = idx & 3;
    const float* s = src + (size_t)frame * CC * HWN;
    float4 v;
    v.x = s[(cq * 4 + 0) * HWN + px];
    v.y = s[(cq * 4 + 1) * HWN + px];
    v.z = s[(cq * 4 + 2) * HWN + px];
    v.w = s[(cq * 4 + 3) * HWN + px];
    dst[(size_t)frame * HWN * 4 + idx] = v;
}

// flows [2][HW] -> interleaved [HW][2]
__global__ __launch_bounds__(256) void transpose_flow_kernel(
    const float* __restrict__ src, float2* __restrict__ dst)
{
    const int px = blockIdx.x * blockDim.x + threadIdx.x;
    const int frame = blockIdx.y + blockIdx.z * LL;
    const float* s = src + (size_t)frame * 2 * HWN;
    float2 v;
    v.x = s[px];
    v.y = s[HWN + px];
    dst[(size_t)frame * HWN + px] = v;
}

// ---------------- scan step kernels (NHWC) ----------------
// 4 lanes per pixel; lane cq owns channels [cq*4, cq*4+4).

__global__ __launch_bounds__(256) void pscan_step_nhwc(
    const float2* __restrict__ srcF,
    const float4* __restrict__ srcI,
    float2* __restrict__ dstF,
    float4* __restrict__ dstI,
    int step)
{
    const int tid = threadIdx.x;
    const int px  = blockIdx.x * 64 + (tid >> 2);
    const int cq  = tid & 3;
    const int t = blockIdx.y;
    const int b = blockIdx.z;
    const int frame = b * LL + t;

    const float4* icur = srcI + (size_t)frame * HWN * 4;
    float4*       dimg = dstI + (size_t)frame * HWN * 4;

    if (t < step) {
        dimg[px * 4 + cq] = icur[px * 4 + cq];
        if (cq == 0)
            dstF[(size_t)frame * HWN + px] = srcF[(size_t)frame * HWN + px];
        return;
    }

    const float2 fc = srcF[(size_t)frame * HWN + px];
    const int x = px % WW;
    const int y = px / WW;
    const Taps tp = make_taps(x, y, fc.x, fc.y);

    const int prev = b * LL + (t - step);
    const float4* iprev = srcI + (size_t)prev * HWN * 4;

    const float4 p00 = iprev[tp.i00 * 4 + cq];
    const float4 p01 = iprev[tp.i01 * 4 + cq];
    const float4 p10 = iprev[tp.i10 * 4 + cq];
    const float4 p11 = iprev[tp.i11 * 4 + cq];
    const float4 c   = icur[px * 4 + cq];

    float4 o;
    o.x = __fadd_rn(c.x, wsum(tp.w00, p00.x, tp.w01, p01.x, tp.w10, p10.x, tp.w11, p11.x));
    o.y = __fadd_rn(c.y, wsum(tp.w00, p00.y, tp.w01, p01.y, tp.w10, p10.y, tp.w11, p11.y));
    o.z = __fadd_rn(c.z, wsum(tp.w00, p00.z, tp.w01, p01.z, tp.w10, p10.z, tp.w11, p11.z));
    o.w = __fadd_rn(c.w, wsum(tp.w00, p00.w, tp.w01, p01.w, tp.w10, p10.w, tp.w11, p11.w));
    dimg[px * 4 + cq] = o;

    if (cq == 0) {
        const float2* fprev = srcF + (size_t)prev * HWN;
        const float2 q00 = fprev[tp.i00];
        const float2 q01 = fprev[tp.i01];
        const float2 q10 = fprev[tp.i10];
        const float2 q11 = fprev[tp.i11];
        float2 of;
        of.x = __fadd_rn(fc.x, wsum(tp.w00, q00.x, tp.w01, q01.x, tp.w10, q10.x, tp.w11, q11.x));
        of.y = __fadd_rn(fc.y, wsum(tp.w00, q00.y, tp.w01, q01.y, tp.w10, q10.y, tp.w11, q11.y));
        dstF[(size_t)frame * HWN + px] = of;
    }
}

// final step (s=16): NHWC in, NCHW out, no flow write
__global__ __launch_bounds__(256) void pscan_final_nhwc(
    const float2* __restrict__ srcF,
    const float4* __restrict__ srcI,
    float* __restrict__ dstI,   // NCHW
    int step)
{
    const int tid = threadIdx.x;
    const int px  = blockIdx.x * 64 + (tid >> 2);
    const int cq  = tid & 3;
    const int t = blockIdx.y;
    const int b = blockIdx.z;
    const int frame = b * LL + t;

    const float4* icur = srcI + (size_t)frame * HWN * 4;
    float* dimg = dstI + (size_t)frame * CC * HWN;

    if (t < step) {
        const float4 c = icur[px * 4 + cq];
        dimg[(cq * 4 + 0) * HWN + px] = c.x;
        dimg[(cq * 4 + 1) * HWN + px] = c.y;
        dimg[(cq * 4 + 2) * HWN + px] = c.z;
        dimg[(cq * 4 + 3) * HWN + px] = c.w;
        return;
    }

    const float2 fc = srcF[(size_t)frame * HWN + px];
    const int x = px % WW;
    const int y = px / WW;
    const Taps tp = make_taps(x, y, fc.x, fc.y);

    const int prev = b * LL + (t - step);
    const float4* iprev = srcI + (size_t)prev * HWN * 4;

    const float4 p00 = iprev[tp.i00 * 4 + cq];
    const float4 p01 = iprev[tp.i01 * 4 + cq];
    const float4 p10 = iprev[tp.i10 * 4 + cq];
    const float4 p11 = iprev[tp.i11 * 4 + cq];
    const float4 c   = icur[px * 4 + cq];

    dimg[(cq * 4 + 0) * HWN + px] =
        __fadd_rn(c.x, wsum(tp.w00, p00.x, tp.w01, p01.x, tp.w10, p10.x, tp.w11, p11.x));
    dimg[(cq * 4 + 1) * HWN + px] =
        __fadd_rn(c.y, wsum(tp.w00, p00.y, tp.w01, p01.y, tp.w10, p10.y, tp.w11, p11.y));
    dimg[(cq * 4 + 2) * HWN + px] =
        __fadd_rn(c.z, wsum(tp.w00, p00.z, tp.w01, p01.z, tp.w10, p10.z, tp.w11, p11.z));
    dimg[(cq * 4 + 3) * HWN + px] =
        __fadd_rn(c.w, wsum(tp.w00, p00.w, tp.w01, p01.w, tp.w10, p10.w, tp.w11, p11.w));
}

extern "C" void kernel_launch(void* const* d_in, const int* in_sizes, int n_in,
                              void* d_out, int out_size)
{
    // Defensive input-order resolution via element counts
    const float* in_flows  = (const float*)d_in[0];  // [B,L,2,H,W]
    const float* in_images = (const float*)d_in[1];  // [B,L,C,H,W]
    if (in_sizes[0] == IMG_ELEMS && in_sizes[1] == FLOW_ELEMS) {
        in_flows  = (const float*)d_in[1];
        in_images = (const float*)d_in[0];
    }
    float* out_images = (float*)d_out;               // [B,L,C,H,W]

    float4 *iA, *iB;
    float2 *fT, *fA, *fB;
    cudaGetSymbolAddress((void**)&iA, g_imgA);
    cudaGetSymbolAddress((void**)&iB, g_imgB);
    cudaGetSymbolAddress((void**)&fT, g_flwT);
    cudaGetSymbolAddress((void**)&fA, g_flwA);
    cudaGetSymbolAddress((void**)&fB, g_flwB);

    // transposes: NCHW -> NHWC / interleaved
    {
        dim3 block(256);
        dim3 gridI(HWN * 4 / 256, LL, BB);   // 576 x 32 x 4
        transpose_img_kernel<<<gridI, block>>>(in_images, iA);
        dim3 gridF(HWN / 256, LL, BB);       // 144 x 32 x 4
        transpose_flow_kernel<<<gridF, block>>>(in_flows, fT);
    }

    dim3 block(256);
    dim3 grid(HWN / 64, LL, BB);   // 576 x 32 x 4 (4 lanes/pixel)

    // step 1:  (fT, iA) -> (fA, iB)
    pscan_step_nhwc<<<grid, block>>>(fT, iA, fA, iB, 1);
    // step 2:  (fA, iB) -> (fB, iA)
    pscan_step_nhwc<<<grid, block>>>(fA, iB, fB, iA, 2);
    // step 4:  (fB, iA) -> (fA, iB)
    pscan_step_nhwc<<<grid, block>>>(fB, iA, fA, iB, 4);
    // step 8:  (fA, iB) -> (fB, iA)
    pscan_step_nhwc<<<grid, block>>>(fA, iB, fB, iA, 8);
    // step 16: (fB, iA) -> d_out (NCHW, images only; flows dead)
    pscan_final_nhwc<<<grid, block>>>(fB, iA, out_images, 16);
}

// round 8
// speedup vs baseline: 2.6943x; 1.1061x over previous
#include <cuda_runtime.h>
#include <math.h>

// Problem dims (fixed by the reference setup_inputs)
#define BB 4
#define LL 32
#define CC 16
#define HH 192
#define WW 192
#define HWN (HH * WW)                    // 36864
#define FLOW_ELEMS (BB * LL * 2 * HWN)   // 9,437,184
#define IMG_ELEMS  (BB * LL * CC * HWN)  // 75,497,472

// Scratch (allocation-free rule: __device__ globals).
// Parity-0 / parity-1 buffers; transposed inputs land in parity 0.
__device__ float4 g_img0[IMG_ELEMS / 4];
__device__ float4 g_img1[IMG_ELEMS / 4];
__device__ float2 g_flw0[FLOW_ELEMS / 2];
__device__ float2 g_flw1[FLOW_ELEMS / 2];

// Exact floor-mod by 2.0, value-identical to jnp.remainder(z, 2.0) in fp32.
__device__ __forceinline__ float floor_mod2(float z) {
    float q = floorf(__fmul_rn(z, 0.5f));
    return __fsub_rn(z, __fmul_rn(2.0f, q));
}

// Which buffer (0/1) holds frame t's live value at the START of level k.
// u(t,k) = #{j<k : 2^j <= t} = min(k, floor(log2 t)+1); parity = u & 1.
__device__ __forceinline__ int parity_at(int t, int k) {
    if (t == 0) return 0;
    int f = 31 - __clz(t);
    int u = min(k, f + 1);
    return u & 1;
}

// Bit-exact coordinate/weight computation (no fma, reference association).
struct Taps {
    int i00, i01, i10, i11;
    float w00, w01, w10, w11;
};
__device__ __forceinline__ Taps make_taps(int x, int y, float f0, float f1) {
    const float C2W = (float)(2.0 / 192.0);
    const float gx = __fsub_rn(__fmul_rn(__fadd_rn((float)x, 0.5f), C2W), 1.0f);
    const float gy = __fsub_rn(__fmul_rn(__fadd_rn((float)y, 0.5f), C2W), 1.0f);

    const float fx_u = __fadd_rn(gx, f0);
    const float fy   = __fadd_rn(gy, f1);
    const float z  = __fadd_rn(fx_u, 1.0f);
    const float fx = __fsub_rn(floor_mod2(z), 1.0f);

    const float ix = __fsub_rn(__fmul_rn(__fmul_rn(__fadd_rn(fx, 1.0f), 0.5f), (float)WW), 0.5f);
    const float iy = __fsub_rn(__fmul_rn(__fmul_rn(__fadd_rn(fy, 1.0f), 0.5f), (float)HH), 0.5f);

    const float x0f = floorf(ix);
    const float y0f = floorf(iy);
    const float wx1 = __fsub_rn(ix, x0f);
    const float wy1 = __fsub_rn(iy, y0f);
    const float wx0 = __fsub_rn(1.0f, wx1);
    const float wy0 = __fsub_rn(1.0f, wy1);

    const int x0 = (int)x0f, y0 = (int)y0f;
    const int x1 = x0 + 1,  y1 = y0 + 1;

    const bool vx0 = (x0 >= 0) & (x0 < WW);
    const bool vx1 = (x1 >= 0) & (x1 < WW);
    const bool vy0 = (y0 >= 0) & (y0 < HH);
    const bool vy1 = (y1 >= 0) & (y1 < HH);

    const int xc0 = min(max(x0, 0), WW - 1);
    const int xc1 = min(max(x1, 0), WW - 1);
    const int yc0 = min(max(y0, 0), HH - 1);
    const int yc1 = min(max(y1, 0), HH - 1);

    Taps tp;
    tp.w00 = __fmul_rn(__fmul_rn(wy0, wx0), (vy0 & vx0) ? 1.0f : 0.0f);
    tp.w01 = __fmul_rn(__fmul_rn(wy0, wx1), (vy0 & vx1) ? 1.0f : 0.0f);
    tp.w10 = __fmul_rn(__fmul_rn(wy1, wx0), (vy1 & vx0) ? 1.0f : 0.0f);
    tp.w11 = __fmul_rn(__fmul_rn(wy1, wx1), (vy1 & vx1) ? 1.0f : 0.0f);
    tp.i00 = yc0 * WW + xc0;
    tp.i01 = yc0 * WW + xc1;
    tp.i10 = yc1 * WW + xc0;
    tp.i11 = yc1 * WW + xc1;
    return tp;
}

// Exact left-assoc weighted sum: ((w00*a + w01*b) + w10*c) + w11*d
__device__ __forceinline__ float wsum(float w00, float a, float w01, float b,
                                      float w10, float c, float w11, float d) {
    return __fadd_rn(
             __fadd_rn(
               __fadd_rn(__fmul_rn(w00, a), __fmul_rn(w01, b)),
               __fmul_rn(w10, c)),
             __fmul_rn(w11, d));
}

// ---------------- transpose kernels (inputs -> parity-0 buffers) ----------------

__global__ __launch_bounds__(256) void transpose_img_kernel(
    const float* __restrict__ src, float4* __restrict__ dst)
{
    const int idx = blockIdx.x * blockDim.x + threadIdx.x;  // [0, HWN*4)
    const int frame = blockIdx.y + blockIdx.z * LL;
    const int px = idx >> 2;
    const int cq = idx & 3;
    const float* s = src + (size_t)frame * CC * HWN;
    float4 v;
    v.x = s[(cq * 4 + 0) * HWN + px];
    v.y = s[(cq * 4 + 1) * HWN + px];
    v.z = s[(cq * 4 + 2) * HWN + px];
    v.w = s[(cq * 4 + 3) * HWN + px];
    dst[(size_t)frame * HWN * 4 + idx] = v;
}

__global__ __launch_bounds__(256) void transpose_flow_kernel(
    const float* __restrict__ src, float2* __restrict__ dst)
{
    const int px = blockIdx.x * blockDim.x + threadIdx.x;
    const int frame = blockIdx.y + blockIdx.z * LL;
    const float* s = src + (size_t)frame * 2 * HWN;
    float2 v;
    v.x = s[px];
    v.y = s[HWN + px];
    dst[(size_t)frame * HWN + px] = v;
}

// ---------------- scan step (NHWC, parity-indirected, 2 px/thread) ----------------
// 4 lanes per pixel (lane cq owns channels [cq*4, cq*4+4)); each thread does 2 pixels.

template <int K, int STEP>
__global__ __launch_bounds__(256) void pscan_step(
    float2* flw0, float2* flw1, float4* img0, float4* img1)
{
    const int t   = blockIdx.y + STEP;          // only frames t >= STEP launched
    const int bz  = blockIdx.z;
    const int tid = threadIdx.x;
    const int cq  = tid & 3;
    const int px0 = blockIdx.x * 128 + (tid >> 2);
    const int px1 = px0 + 64;

    const int frame = bz * LL + t;
    const int prevf = frame - STEP;

    const int pc = parity_at(t, K);
    const int pp = parity_at(t - STEP, K);

    const float2* fcur  = (pc ? flw1 : flw0) + (size_t)frame * HWN;
    const float4* icur  = (pc ? img1 : img0) + (size_t)frame * (HWN * 4);
    const float2* fprev = (pp ? flw1 : flw0) + (size_t)prevf * HWN;
    const float4* iprev = (pp ? img1 : img0) + (size_t)prevf * (HWN * 4);
    float2*       fdst  = (pc ? flw0 : flw1) + (size_t)frame * HWN;
    float4*       idst  = (pc ? img0 : img1) + (size_t)frame * (HWN * 4);

    const float2 fc0 = __ldg(&fcur[px0]);
    const float2 fc1 = __ldg(&fcur[px1]);
    const Taps tp0 = make_taps(px0 % WW, px0 / WW, fc0.x, fc0.y);
    const Taps tp1 = make_taps(px1 % WW, px1 / WW, fc1.x, fc1.y);

    // batch all independent loads for MLP
    const float4 a00 = __ldg(&iprev[tp0.i00 * 4 + cq]);
    const float4 a01 = __ldg(&iprev[tp0.i01 * 4 + cq]);
    const float4 a10 = __ldg(&iprev[tp0.i10 * 4 + cq]);
    const float4 a11 = __ldg(&iprev[tp0.i11 * 4 + cq]);
    const float4 e00 = __ldg(&iprev[tp1.i00 * 4 + cq]);
    const float4 e01 = __ldg(&iprev[tp1.i01 * 4 + cq]);
    const float4 e10 = __ldg(&iprev[tp1.i10 * 4 + cq]);
    const float4 e11 = __ldg(&iprev[tp1.i11 * 4 + cq]);
    const float4 c0  = __ldg(&icur[px0 * 4 + cq]);
    const float4 c1  = __ldg(&icur[px1 * 4 + cq]);

    float4 o0;
    o0.x = __fadd_rn(c0.x, wsum(tp0.w00, a00.x, tp0.w01, a01.x, tp0.w10, a10.x, tp0.w11, a11.x));
    o0.y = __fadd_rn(c0.y, wsum(tp0.w00, a00.y, tp0.w01, a01.y, tp0.w10, a10.y, tp0.w11, a11.y));
    o0.z = __fadd_rn(c0.z, wsum(tp0.w00, a00.z, tp0.w01, a01.z, tp0.w10, a10.z, tp0.w11, a11.z));
    o0.w = __fadd_rn(c0.w, wsum(tp0.w00, a00.w, tp0.w01, a01.w, tp0.w10, a10.w, tp0.w11, a11.w));
    idst[px0 * 4 + cq] = o0;

    float4 o1;
    o1.x = __fadd_rn(c1.x, wsum(tp1.w00, e00.x, tp1.w01, e01.x, tp1.w10, e10.x, tp1.w11, e11.x));
    o1.y = __fadd_rn(c1.y, wsum(tp1.w00, e00.y, tp1.w01, e01.y, tp1.w10, e10.y, tp1.w11, e11.y));
    o1.z = __fadd_rn(c1.z, wsum(tp1.w00, e00.z, tp1.w01, e01.z, tp1.w10, e10.z, tp1.w11, e11.z));
    o1.w = __fadd_rn(c1.w, wsum(tp1.w00, e00.w, tp1.w01, e01.w, tp1.w10, e10.w, tp1.w11, e11.w));
    idst[px1 * 4 + cq] = o1;

    if (cq == 0) {
        // flow path must stay exactly left-associative (feeds wrap discontinuity)
        const float2 q00 = __ldg(&fprev[tp0.i00]);
        const float2 q01 = __ldg(&fprev[tp0.i01]);
        const float2 q10 = __ldg(&fprev[tp0.i10]);
        const float2 q11 = __ldg(&fprev[tp0.i11]);
        const float2 r00 = __ldg(&fprev[tp1.i00]);
        const float2 r01 = __ldg(&fprev[tp1.i01]);
        const float2 r10 = __ldg(&fprev[tp1.i10]);
        const float2 r11 = __ldg(&fprev[tp1.i11]);
        float2 of0, of1;
        of0.x = __fadd_rn(fc0.x, wsum(tp0.w00, q00.x, tp0.w01, q01.x, tp0.w10, q10.x, tp0.w11, q11.x));
        of0.y = __fadd_rn(fc0.y, wsum(tp0.w00, q00.y, tp0.w01, q01.y, tp0.w10, q10.y, tp0.w11, q11.y));
        of1.x = __fadd_rn(fc1.x, wsum(tp1.w00, r00.x, tp1.w01, r01.x, tp1.w10, r10.x, tp1.w11, r11.x));
        of1.y = __fadd_rn(fc1.y, wsum(tp1.w00, r00.y, tp1.w01, r01.y, tp1.w10, r10.y, tp1.w11, r11.y));
        fdst[px0] = of0;
        fdst[px1] = of1;
    }
}

// final level (K=4, STEP=16): reads parity buffers, writes NCHW d_out (all frames)
__global__ __launch_bounds__(256) void pscan_final(
    float2* flw0, float2* flw1, float4* img0, float4* img1,
    float* __restrict__ out)
{
    const int t   = blockIdx.y;
    const int bz  = blockIdx.z;
    const int tid = threadIdx.x;
    const int cq  = tid & 3;
    const int px0 = blockIdx.x * 128 + (tid >> 2);
    const int px1 = px0 + 64;

    const int frame = bz * LL + t;
    const int pc = parity_at(t, 4);
    const float4* icur = (pc ? img1 : img0) + (size_t)frame * (HWN * 4);
    float* dimg = out + (size_t)frame * CC * HWN;

    if (t < 16) {
        // prefix frames: NHWC -> NCHW copy of their live value
        const float4 c0 = __ldg(&icur[px0 * 4 + cq]);
        const float4 c1 = __ldg(&icur[px1 * 4 + cq]);
        dimg[(cq * 4 + 0) * HWN + px0] = c0.x;
        dimg[(cq * 4 + 1) * HWN + px0] = c0.y;
        dimg[(cq * 4 + 2) * HWN + px0] = c0.z;
        dimg[(cq * 4 + 3) * HWN + px0] = c0.w;
        dimg[(cq * 4 + 0) * HWN + px1] = c1.x;
        dimg[(cq * 4 + 1) * HWN + px1] = c1.y;
        dimg[(cq * 4 + 2) * HWN + px1] = c1.z;
        dimg[(cq * 4 + 3) * HWN + px1] = c1.w;
        return;
    }

    const int prevf = frame - 16;
    const int pp = parity_at(t - 16, 4);
    const float2* fcur  = (pc ? flw1 : flw0) + (size_t)frame * HWN;
    const float4* iprev = (pp ? img1 : img0) + (size_t)prevf * (HWN * 4);

    const float2 fc0 = __ldg(&fcur[px0]);
    const float2 fc1 = __ldg(&fcur[px1]);
    const Taps tp0 = make_taps(px0 % WW, px0 / WW, fc0.x, fc0.y);
    const Taps tp1 = make_taps(px1 % WW, px1 / WW, fc1.x, fc1.y);

    const float4 a00 = __ldg(&iprev[tp0.i00 * 4 + cq]);
    const float4 a01 = __ldg(&iprev[tp0.i01 * 4 + cq]);
    const float4 a10 = __ldg(&iprev[tp0.i10 * 4 + cq]);
    const float4 a11 = __ldg(&iprev[tp0.i11 * 4 + cq]);
    const float4 e00 = __ldg(&iprev[tp1.i00 * 4 + cq]);
    const float4 e01 = __ldg(&iprev[tp1.i01 * 4 + cq]);
    const float4 e10 = __ldg(&iprev[tp1.i10 * 4 + cq]);
    const float4 e11 = __ldg(&iprev[tp1.i11 * 4 + cq]);
    const float4 c0  = __ldg(&icur[px0 * 4 + cq]);
    const float4 c1  = __ldg(&icur[px1 * 4 + cq]);

    dimg[(cq * 4 + 0) * HWN + px0] =
        __fadd_rn(c0.x, wsum(tp0.w00, a00.x, tp0.w01, a01.x, tp0.w10, a10.x, tp0.w11, a11.x));
    dimg[(cq * 4 + 1) * HWN + px0] =
        __fadd_rn(c0.y, wsum(tp0.w00, a00.y, tp0.w01, a01.y, tp0.w10, a10.y, tp0.w11, a11.y));
    dimg[(cq * 4 + 2) * HWN + px0] =
        __fadd_rn(c0.z, wsum(tp0.w00, a00.z, tp0.w01, a01.z, tp0.w10, a10.z, tp0.w11, a11.z));
    dimg[(cq * 4 + 3) * HWN + px0] =
        __fadd_rn(c0.w, wsum(tp0.w00, a00.w, tp0.w01, a01.w, tp0.w10, a10.w, tp0.w11, a11.w));

    dimg[(cq * 4 + 0) * HWN + px1] =
        __fadd_rn(c1.x, wsum(tp1.w00, e00.x, tp1.w01, e01.x, tp1.w10, e10.x, tp1.w11, e11.x));
    dimg[(cq * 4 + 1) * HWN + px1] =
        __fadd_rn(c1.y, wsum(tp1.w00, e00.y, tp1.w01, e01.y, tp1.w10, e10.y, tp1.w11, e11.y));
    dimg[(cq * 4 + 2) * HWN + px1] =
        __fadd_rn(c1.z, wsum(tp1.w00, e00.z, tp1.w01, e01.z, tp1.w10, e10.z, tp1.w11, e11.z));
    dimg[(cq * 4 + 3) * HWN + px1] =
        __fadd_rn(c1.w, wsum(tp1.w00, e00.w, tp1.w01, e01.w, tp1.w10, e10.w, tp1.w11, e11.w));
}

extern "C" void kernel_launch(void* const* d_in, const int* in_sizes, int n_in,
                              void* d_out, int out_size)
{
    // Defensive input-order resolution via element counts
    const float* in_flows  = (const float*)d_in[0];  // [B,L,2,H,W]
    const float* in_images = (const float*)d_in[1];  // [B,L,C,H,W]
    if (in_sizes[0] == IMG_ELEMS && in_sizes[1] == FLOW_ELEMS) {
        in_flows  = (const float*)d_in[1];
        in_images = (const float*)d_in[0];
    }
    float* out_images = (float*)d_out;               // [B,L,C,H,W]

    float4 *i0, *i1;
    float2 *f0, *f1;
    cudaGetSymbolAddress((void**)&i0, g_img0);
    cudaGetSymbolAddress((void**)&i1, g_img1);
    cudaGetSymbolAddress((void**)&f0, g_flw0);
    cudaGetSymbolAddress((void**)&f1, g_flw1);

    dim3 block(256);

    // transposes: NCHW -> NHWC / interleaved, into parity-0 buffers
    {
        dim3 gridI(HWN * 4 / 256, LL, BB);
        transpose_img_kernel<<<gridI, block>>>(in_images, i0);
        dim3 gridF(HWN / 256, LL, BB);
        transpose_flow_kernel<<<gridF, block>>>(in_flows, f0);
    }

    // scan levels; only frames t >= step launched (prefix never copied)
    {
        dim3 g1(HWN / 128, LL - 1, BB);
        pscan_step<0, 1><<<g1, block>>>(f0, f1, i0, i1);
        dim3 g2(HWN / 128, LL - 2, BB);
        pscan_step<1, 2><<<g2, block>>>(f0, f1, i0, i1);
        dim3 g4(HWN / 128, LL - 4, BB);
        pscan_step<2, 4><<<g4, block>>>(f0, f1, i0, i1);
        dim3 g8(HWN / 128, LL - 8, BB);
        pscan_step<3, 8><<<g8, block>>>(f0, f1, i0, i1);
    }

    // final level: parity-resolved read, NCHW output, flows dead
    {
        dim3 gf(HWN / 128, LL, BB);
        pscan_final<<<gf, block>>>(f0, f1, i0, i1, out_images);
    }
}

// round 9
// speedup vs baseline: 2.9384x; 1.0906x over previous
#include <cuda_runtime.h>
#include <math.h>

// Problem dims (fixed by the reference setup_inputs)
#define BB 4
#define LL 32
#define CC 16
#define HH 192
#define WW 192
#define HWN (HH * WW)                    // 36864
#define FLOW_ELEMS (BB * LL * 2 * HWN)   // 9,437,184
#define IMG_ELEMS  (BB * LL * CC * HWN)  // 75,497,472

// Scratch (allocation-free rule: __device__ globals).
// Parity-0 / parity-1 buffers; transposed inputs land in parity 0.
__device__ float4 g_img0[IMG_ELEMS / 4];
__device__ float4 g_img1[IMG_ELEMS / 4];
__device__ float2 g_flw0[FLOW_ELEMS / 2];
__device__ float2 g_flw1[FLOW_ELEMS / 2];

// Exact floor-mod by 2.0, value-identical to jnp.remainder(z, 2.0) in fp32.
__device__ __forceinline__ float floor_mod2(float z) {
    float q = floorf(__fmul_rn(z, 0.5f));
    return __fsub_rn(z, __fmul_rn(2.0f, q));
}

// Which buffer (0/1) holds frame t's live value at the START of level k.
// u(t,k) = #{j<k : 2^j <= t} = min(k, floor(log2 t)+1); parity = u & 1.
__device__ __forceinline__ int parity_at(int t, int k) {
    if (t == 0) return 0;
    int f = 31 - __clz(t);
    int u = min(k, f + 1);
    return u & 1;
}

// Bit-exact coordinate/weight computation (no fma, reference association).
struct Taps {
    int i00, i01, i10, i11;
    float w00, w01, w10, w11;
};
__device__ __forceinline__ Taps make_taps(int x, int y, float f0, float f1) {
    const float C2W = (float)(2.0 / 192.0);
    const float gx = __fsub_rn(__fmul_rn(__fadd_rn((float)x, 0.5f), C2W), 1.0f);
    const float gy = __fsub_rn(__fmul_rn(__fadd_rn((float)y, 0.5f), C2W), 1.0f);

    const float fx_u = __fadd_rn(gx, f0);
    const float fy   = __fadd_rn(gy, f1);
    const float z  = __fadd_rn(fx_u, 1.0f);
    const float fx = __fsub_rn(floor_mod2(z), 1.0f);

    const float ix = __fsub_rn(__fmul_rn(__fmul_rn(__fadd_rn(fx, 1.0f), 0.5f), (float)WW), 0.5f);
    const float iy = __fsub_rn(__fmul_rn(__fmul_rn(__fadd_rn(fy, 1.0f), 0.5f), (float)HH), 0.5f);

    const float x0f = floorf(ix);
    const float y0f = floorf(iy);
    const float wx1 = __fsub_rn(ix, x0f);
    const float wy1 = __fsub_rn(iy, y0f);
    const float wx0 = __fsub_rn(1.0f, wx1);
    const float wy0 = __fsub_rn(1.0f, wy1);

    const int x0 = (int)x0f, y0 = (int)y0f;
    const int x1 = x0 + 1,  y1 = y0 + 1;

    const bool vx0 = (x0 >= 0) & (x0 < WW);
    const bool vx1 = (x1 >= 0) & (x1 < WW);
    const bool vy0 = (y0 >= 0) & (y0 < HH);
    const bool vy1 = (y1 >= 0) & (y1 < HH);

    const int xc0 = min(max(x0, 0), WW - 1);
    const int xc1 = min(max(x1, 0), WW - 1);
    const int yc0 = min(max(y0, 0), HH - 1);
    const int yc1 = min(max(y1, 0), HH - 1);

    Taps tp;
    tp.w00 = __fmul_rn(__fmul_rn(wy0, wx0), (vy0 & vx0) ? 1.0f : 0.0f);
    tp.w01 = __fmul_rn(__fmul_rn(wy0, wx1), (vy0 & vx1) ? 1.0f : 0.0f);
    tp.w10 = __fmul_rn(__fmul_rn(wy1, wx0), (vy1 & vx0) ? 1.0f : 0.0f);
    tp.w11 = __fmul_rn(__fmul_rn(wy1, wx1), (vy1 & vx1) ? 1.0f : 0.0f);
    tp.i00 = yc0 * WW + xc0;
    tp.i01 = yc0 * WW + xc1;
    tp.i10 = yc1 * WW + xc0;
    tp.i11 = yc1 * WW + xc1;
    return tp;
}

__device__ __forceinline__ int tap_sel(const Taps& tp, int j) {
    return j == 0 ? tp.i00 : (j == 1 ? tp.i01 : (j == 2 ? tp.i10 : tp.i11));
}

// Exact left-assoc weighted sum: ((w00*a + w01*b) + w10*c) + w11*d
__device__ __forceinline__ float wsum(float w00, float a, float w01, float b,
                                      float w10, float c, float w11, float d) {
    return __fadd_rn(
             __fadd_rn(
               __fadd_rn(__fmul_rn(w00, a), __fmul_rn(w01, b)),
               __fmul_rn(w10, c)),
             __fmul_rn(w11, d));
}

// ---------------- transpose kernels (inputs -> parity-0 buffers) ----------------

__global__ __launch_bounds__(256) void transpose_img_kernel(
    const float* __restrict__ src, float4* __restrict__ dst)
{
    const int idx = blockIdx.x * blockDim.x + threadIdx.x;  // [0, HWN*4)
    const int frame = blockIdx.y + blockIdx.z * LL;
    const int px = idx >> 2;
    const int cq = idx & 3;
    const float* s = src + (size_t)frame * CC * HWN;
    float4 v;
    v.x = s[(cq * 4 + 0) * HWN + px];
    v.y = s[(cq * 4 + 1) * HWN + px];
    v.z = s[(cq * 4 + 2) * HWN + px];
    v.w = s[(cq * 4 + 3) * HWN + px];
    dst[(size_t)frame * HWN * 4 + idx] = v;
}

__global__ __launch_bounds__(256) void transpose_flow_kernel(
    const float* __restrict__ src, float2* __restrict__ dst)
{
    const int px = blockIdx.x * blockDim.x + threadIdx.x;
    const int frame = blockIdx.y + blockIdx.z * LL;
    const float* s = src + (size_t)frame * 2 * HWN;
    float2 v;
    v.x = s[px];
    v.y = s[HWN + px];
    dst[(size_t)frame * HWN + px] = v;
}

// ---------------- scan step (NHWC, parity-indirected, 2 px/thread) ----------------
// 4 lanes per pixel (lane cq owns channels [cq*4, cq*4+4)); each thread does 2 pixels.
// Flow gathers are lane-distributed (tap j loaded by lane cq==j) and shuffled to
// the quad leader, which does the bit-exact left-associative arithmetic.

template <int K, int STEP>
__global__ __launch_bounds__(256, 5) void pscan_step(
    float2* flw0, float2* flw1, float4* img0, float4* img1)
{
    const int t   = blockIdx.y + STEP;          // only frames t >= STEP launched
    const int bz  = blockIdx.z;
    const int tid = threadIdx.x;
    const int cq  = tid & 3;
    const int px0 = blockIdx.x * 128 + (tid >> 2);
    const int px1 = px0 + 64;

    const int frame = bz * LL + t;
    const int prevf = frame - STEP;

    const int pc = parity_at(t, K);
    const int pp = parity_at(t - STEP, K);

    const float2* fcur  = (pc ? flw1 : flw0) + (size_t)frame * HWN;
    const float4* icur  = (pc ? img1 : img0) + (size_t)frame * (HWN * 4);
    const float2* fprev = (pp ? flw1 : flw0) + (size_t)prevf * HWN;
    const float4* iprev = (pp ? img1 : img0) + (size_t)prevf * (HWN * 4);
    float2*       fdst  = (pc ? flw0 : flw1) + (size_t)frame * HWN;
    float4*       idst  = (pc ? img0 : img1) + (size_t)frame * (HWN * 4);

    const float2 fc0 = __ldg(&fcur[px0]);
    const float2 fc1 = __ldg(&fcur[px1]);
    const Taps tp0 = make_taps(px0 % WW, px0 / WW, fc0.x, fc0.y);
    const Taps tp1 = make_taps(px1 % WW, px1 / WW, fc1.x, fc1.y);

    // lane-distributed flow tap loads (all 4 lanes of a quad issue one tap each)
    const float2 qf = __ldg(&fprev[tap_sel(tp0, cq)]);
    const float2 rf = __ldg(&fprev[tap_sel(tp1, cq)]);

    // batch all independent image loads for MLP
    const float4 a00 = __ldg(&iprev[tp0.i00 * 4 + cq]);
    const float4 a01 = __ldg(&iprev[tp0.i01 * 4 + cq]);
    const float4 a10 = __ldg(&iprev[tp0.i10 * 4 + cq]);
    const float4 a11 = __ldg(&iprev[tp0.i11 * 4 + cq]);
    const float4 e00 = __ldg(&iprev[tp1.i00 * 4 + cq]);
    const float4 e01 = __ldg(&iprev[tp1.i01 * 4 + cq]);
    const float4 e10 = __ldg(&iprev[tp1.i10 * 4 + cq]);
    const float4 e11 = __ldg(&iprev[tp1.i11 * 4 + cq]);
    const float4 c0  = __ldg(&icur[px0 * 4 + cq]);
    const float4 c1  = __ldg(&icur[px1 * 4 + cq]);

    // shuffle flow taps to quad leader (bits only; arithmetic unchanged)
    const unsigned FULL = 0xffffffffu;
    const float q00x = qf.x,                          q00y = qf.y;
    const float q01x = __shfl_down_sync(FULL, qf.x, 1), q01y = __shfl_down_sync(FULL, qf.y, 1);
    const float q10x = __shfl_down_sync(FULL, qf.x, 2), q10y = __shfl_down_sync(FULL, qf.y, 2);
    const float q11x = __shfl_down_sync(FULL, qf.x, 3), q11y = __shfl_down_sync(FULL, qf.y, 3);
    const float r00x = rf.x,                          r00y = rf.y;
    const float r01x = __shfl_down_sync(FULL, rf.x, 1), r01y = __shfl_down_sync(FULL, rf.y, 1);
    const float r10x = __shfl_down_sync(FULL, rf.x, 2), r10y = __shfl_down_sync(FULL, rf.y, 2);
    const float r11x = __shfl_down_sync(FULL, rf.x, 3), r11y = __shfl_down_sync(FULL, rf.y, 3);

    float4 o0;
    o0.x = __fadd_rn(c0.x, wsum(tp0.w00, a00.x, tp0.w01, a01.x, tp0.w10, a10.x, tp0.w11, a11.x));
    o0.y = __fadd_rn(c0.y, wsum(tp0.w00, a00.y, tp0.w01, a01.y, tp0.w10, a10.y, tp0.w11, a11.y));
    o0.z = __fadd_rn(c0.z, wsum(tp0.w00, a00.z, tp0.w01, a01.z, tp0.w10, a10.z, tp0.w11, a11.z));
    o0.w = __fadd_rn(c0.w, wsum(tp0.w00, a00.w, tp0.w01, a01.w, tp0.w10, a10.w, tp0.w11, a11.w));
    idst[px0 * 4 + cq] = o0;

    float4 o1;
    o1.x = __fadd_rn(c1.x, wsum(tp1.w00, e00.x, tp1.w01, e01.x, tp1.w10, e10.x, tp1.w11, e11.x));
    o1.y = __fadd_rn(c1.y, wsum(tp1.w00, e00.y, tp1.w01, e01.y, tp1.w10, e10.y, tp1.w11, e11.y));
    o1.z = __fadd_rn(c1.z, wsum(tp1.w00, e00.z, tp1.w01, e01.z, tp1.w10, e10.z, tp1.w11, e11.z));
    o1.w = __fadd_rn(c1.w, wsum(tp1.w00, e00.w, tp1.w01, e01.w, tp1.w10, e10.w, tp1.w11, e11.w));
    idst[px1 * 4 + cq] = o1;

    if (cq == 0) {
        float2 of0, of1;
        of0.x = __fadd_rn(fc0.x, wsum(tp0.w00, q00x, tp0.w01, q01x, tp0.w10, q10x, tp0.w11, q11x));
        of0.y = __fadd_rn(fc0.y, wsum(tp0.w00, q00y, tp0.w01, q01y, tp0.w10, q10y, tp0.w11, q11y));
        of1.x = __fadd_rn(fc1.x, wsum(tp1.w00, r00x, tp1.w01, r01x, tp1.w10, r10x, tp1.w11, r11x));
        of1.y = __fadd_rn(fc1.y, wsum(tp1.w00, r00y, tp1.w01, r01y, tp1.w10, r10y, tp1.w11, r11y));
        fdst[px0] = of0;
        fdst[px1] = of1;
    }
}

// final level (K=4, STEP=16): reads parity buffers, writes NCHW d_out (all frames)
__global__ __launch_bounds__(256, 5) void pscan_final(
    float2* flw0, float2* flw1, float4* img0, float4* img1,
    float* __restrict__ out)
{
    const int t   = blockIdx.y;
    const int bz  = blockIdx.z;
    const int tid = threadIdx.x;
    const int cq  = tid & 3;
    const int px0 = blockIdx.x * 128 + (tid >> 2);
    const int px1 = px0 + 64;

    const int frame = bz * LL + t;
    const int pc = parity_at(t, 4);
    const float4* icur = (pc ? img1 : img0) + (size_t)frame * (HWN * 4);
    float* dimg = out + (size_t)frame * CC * HWN;

    if (t < 16) {
        // prefix frames: NHWC -> NCHW copy of their live value
        const float4 c0 = __ldg(&icur[px0 * 4 + cq]);
        const float4 c1 = __ldg(&icur[px1 * 4 + cq]);
        dimg[(cq * 4 + 0) * HWN + px0] = c0.x;
        dimg[(cq * 4 + 1) * HWN + px0] = c0.y;
        dimg[(cq * 4 + 2) * HWN + px0] = c0.z;
        dimg[(cq * 4 + 3) * HWN + px0] = c0.w;
        dimg[(cq * 4 + 0) * HWN + px1] = c1.x;
        dimg[(cq * 4 + 1) * HWN + px1] = c1.y;
        dimg[(cq * 4 + 2) * HWN + px1] = c1.z;
        dimg[(cq * 4 + 3) * HWN + px1] = c1.w;
        return;
    }

    const int prevf = frame - 16;
    const int pp = parity_at(t - 16, 4);
    const float2* fcur  = (pc ? flw1 : flw0) + (size_t)frame * HWN;
    const float4* iprev = (pp ? img1 : img0) + (size_t)prevf * (HWN * 4);

    const float2 fc0 = __ldg(&fcur[px0]);
    const float2 fc1 = __ldg(&fcur[px1]);
    const Taps tp0 = make_taps(px0 % WW, px0 / WW, fc0.x, fc0.y);
    const Taps tp1 = make_taps(px1 % WW, px1 / WW, fc1.x, fc1.y);

    const float4 a00 = __ldg(&iprev[tp0.i00 * 4 + cq]);
    const float4 a01 = __ldg(&iprev[tp0.i01 * 4 + cq]);
    const float4 a10 = __ldg(&iprev[tp0.i10 * 4 + cq]);
    const float4 a11 = __ldg(&iprev[tp0.i11 * 4 + cq]);
    const float4 e00 = __ldg(&iprev[tp1.i00 * 4 + cq]);
    const float4 e01 = __ldg(&iprev[tp1.i01 * 4 + cq]);
    const float4 e10 = __ldg(&iprev[tp1.i10 * 4 + cq]);
    const float4 e11 = __ldg(&iprev[tp1.i11 * 4 + cq]);
    const float4 c0  = __ldg(&icur[px0 * 4 + cq]);
    const float4 c1  = __ldg(&icur[px1 * 4 + cq]);

    dimg[(cq * 4 + 0) * HWN + px0] =
        __fadd_rn(c0.x, wsum(tp0.w00, a00.x, tp0.w01, a01.x, tp0.w10, a10.x, tp0.w11, a11.x));
    dimg[(cq * 4 + 1) * HWN + px0] =
        __fadd_rn(c0.y, wsum(tp0.w00, a00.y, tp0.w01, a01.y, tp0.w10, a10.y, tp0.w11, a11.y));
    dimg[(cq * 4 + 2) * HWN + px0] =
        __fadd_rn(c0.z, wsum(tp0.w00, a00.z, tp0.w01, a01.z, tp0.w10, a10.z, tp0.w11, a11.z));
    dimg[(cq * 4 + 3) * HWN + px0] =
        __fadd_rn(c0.w, wsum(tp0.w00, a00.w, tp0.w01, a01.w, tp0.w10, a10.w, tp0.w11, a11.w));

    dimg[(cq * 4 + 0) * HWN + px1] =
        __fadd_rn(c1.x, wsum(tp1.w00, e00.x, tp1.w01, e01.x, tp1.w10, e10.x, tp1.w11, e11.x));
    dimg[(cq * 4 + 1) * HWN + px1] =
        __fadd_rn(c1.y, wsum(tp1.w00, e00.y, tp1.w01, e01.y, tp1.w10, e10.y, tp1.w11, e11.y));
    dimg[(cq * 4 + 2) * HWN + px1] =
        __fadd_rn(c1.z, wsum(tp1.w00, e00.z, tp1.w01, e01.z, tp1.w10, e10.z, tp1.w11, e11.z));
    dimg[(cq * 4 + 3) * HWN + px1] =
        __fadd_rn(c1.w, wsum(tp1.w00, e00.w, tp1.w01, e01.w, tp1.w10, e10.w, tp1.w11, e11.w));
}

extern "C" void kernel_launch(void* const* d_in, const int* in_sizes, int n_in,
                              void* d_out, int out_size)
{
    // Defensive input-order resolution via element counts
    const float* in_flows  = (const float*)d_in[0];  // [B,L,2,H,W]
    const float* in_images = (const float*)d_in[1];  // [B,L,C,H,W]
    if (in_sizes[0] == IMG_ELEMS && in_sizes[1] == FLOW_ELEMS) {
        in_flows  = (const float*)d_in[1];
        in_images = (const float*)d_in[0];
    }
    float* out_images = (float*)d_out;               // [B,L,C,H,W]

    float4 *i0, *i1;
    float2 *f0, *f1;
    cudaGetSymbolAddress((void**)&i0, g_img0);
    cudaGetSymbolAddress((void**)&i1, g_img1);
    cudaGetSymbolAddress((void**)&f0, g_flw0);
    cudaGetSymbolAddress((void**)&f1, g_flw1);

    dim3 block(256);

    // transposes: NCHW -> NHWC / interleaved, into parity-0 buffers
    {
        dim3 gridI(HWN * 4 / 256, LL, BB);
        transpose_img_kernel<<<gridI, block>>>(in_images, i0);
        dim3 gridF(HWN / 256, LL, BB);
        transpose_flow_kernel<<<gridF, block>>>(in_flows, f0);
    }

    // scan levels; only frames t >= step launched (prefix never copied)
    {
        dim3 g1(HWN / 128, LL - 1, BB);
        pscan_step<0, 1><<<g1, block>>>(f0, f1, i0, i1);
        dim3 g2(HWN / 128, LL - 2, BB);
        pscan_step<1, 2><<<g2, block>>>(f0, f1, i0, i1);
        dim3 g4(HWN / 128, LL - 4, BB);
        pscan_step<2, 4><<<g4, block>>>(f0, f1, i0, i1);
        dim3 g8(HWN / 128, LL - 8, BB);
        pscan_step<3, 8><<<g8, block>>>(f0, f1, i0, i1);
    }

    // final level: parity-resolved read, NCHW output, flows dead
    {
        dim3 gf(HWN / 128, LL, BB);
        pscan_final<<<gf, block>>>(f0, f1, i0, i1, out_images);
    }
}

// round 10
// speedup vs baseline: 2.9448x; 1.0022x over previous
#include <cuda_runtime.h>
#include <math.h>

// Problem dims (fixed by the reference setup_inputs)
#define BB 4
#define LL 32
#define CC 16
#define HH 192
#define WW 192
#define HWN (HH * WW)                    // 36864
#define FLOW_ELEMS (BB * LL * 2 * HWN)   // 9,437,184
#define IMG_ELEMS  (BB * LL * CC * HWN)  // 75,497,472
#define PAD 17                           // smem row pad (floats) -> conflict-free

// Scratch (allocation-free rule: __device__ globals).
// Parity-0 / parity-1 buffers; transposed inputs land in parity 0.
__device__ float4 g_img0[IMG_ELEMS / 4];
__device__ float4 g_img1[IMG_ELEMS / 4];
__device__ float2 g_flw0[FLOW_ELEMS / 2];
__device__ float2 g_flw1[FLOW_ELEMS / 2];

// Exact floor-mod by 2.0, value-identical to jnp.remainder(z, 2.0) in fp32.
__device__ __forceinline__ float floor_mod2(float z) {
    float q = floorf(__fmul_rn(z, 0.5f));
    return __fsub_rn(z, __fmul_rn(2.0f, q));
}

// Which buffer (0/1) holds frame t's live value at the START of level k.
// u(t,k) = #{j<k : 2^j <= t} = min(k, floor(log2 t)+1); parity = u & 1.
__device__ __forceinline__ int parity_at(int t, int k) {
    if (t == 0) return 0;
    int f = 31 - __clz(t);
    int u = min(k, f + 1);
    return u & 1;
}

// Bit-exact coordinate/weight computation (no fma, reference association).
struct Taps {
    int i00, i01, i10, i11;
    float w00, w01, w10, w11;
};
__device__ __forceinline__ Taps make_taps(int x, int y, float f0, float f1) {
    const float C2W = (float)(2.0 / 192.0);
    const float gx = __fsub_rn(__fmul_rn(__fadd_rn((float)x, 0.5f), C2W), 1.0f);
    const float gy = __fsub_rn(__fmul_rn(__fadd_rn((float)y, 0.5f), C2W), 1.0f);

    const float fx_u = __fadd_rn(gx, f0);
    const float fy   = __fadd_rn(gy, f1);
    const float z  = __fadd_rn(fx_u, 1.0f);
    const float fx = __fsub_rn(floor_mod2(z), 1.0f);

    const float ix = __fsub_rn(__fmul_rn(__fmul_rn(__fadd_rn(fx, 1.0f), 0.5f), (float)WW), 0.5f);
    const float iy = __fsub_rn(__fmul_rn(__fmul_rn(__fadd_rn(fy, 1.0f), 0.5f), (float)HH), 0.5f);

    const float x0f = floorf(ix);
    const float y0f = floorf(iy);
    const float wx1 = __fsub_rn(ix, x0f);
    const float wy1 = __fsub_rn(iy, y0f);
    const float wx0 = __fsub_rn(1.0f, wx1);
    const float wy0 = __fsub_rn(1.0f, wy1);

    const int x0 = (int)x0f, y0 = (int)y0f;
    const int x1 = x0 + 1,  y1 = y0 + 1;

    const bool vx0 = (x0 >= 0) & (x0 < WW);
    const bool vx1 = (x1 >= 0) & (x1 < WW);
    const bool vy0 = (y0 >= 0) & (y0 < HH);
    const bool vy1 = (y1 >= 0) & (y1 < HH);

    const int xc0 = min(max(x0, 0), WW - 1);
    const int xc1 = min(max(x1, 0), WW - 1);
    const int yc0 = min(max(y0, 0), HH - 1);
    const int yc1 = min(max(y1, 0), HH - 1);

    Taps tp;
    tp.w00 = __fmul_rn(__fmul_rn(wy0, wx0), (vy0 & vx0) ? 1.0f : 0.0f);
    tp.w01 = __fmul_rn(__fmul_rn(wy0, wx1), (vy0 & vx1) ? 1.0f : 0.0f);
    tp.w10 = __fmul_rn(__fmul_rn(wy1, wx0), (vy1 & vx0) ? 1.0f : 0.0f);
    tp.w11 = __fmul_rn(__fmul_rn(wy1, wx1), (vy1 & vx1) ? 1.0f : 0.0f);
    tp.i00 = yc0 * WW + xc0;
    tp.i01 = yc0 * WW + xc1;
    tp.i10 = yc1 * WW + xc0;
    tp.i11 = yc1 * WW + xc1;
    return tp;
}

__device__ __forceinline__ int tap_sel(const Taps& tp, int j) {
    return j == 0 ? tp.i00 : (j == 1 ? tp.i01 : (j == 2 ? tp.i10 : tp.i11));
}

// Exact left-assoc weighted sum: ((w00*a + w01*b) + w10*c) + w11*d
__device__ __forceinline__ float wsum(float w00, float a, float w01, float b,
                                      float w10, float c, float w11, float d) {
    return __fadd_rn(
             __fadd_rn(
               __fadd_rn(__fmul_rn(w00, a), __fmul_rn(w01, b)),
               __fmul_rn(w10, c)),
             __fmul_rn(w11, d));
}

// ---------------- transpose kernels (inputs -> parity-0 buffers) ----------------

// images NCHW -> NHWC, smem-staged: coalesced 128B plane reads, float4 NHWC writes.
__global__ __launch_bounds__(256) void transpose_img_kernel(
    const float* __restrict__ src, float4* __restrict__ dst)
{
    __shared__ float sm[64 * PAD];
    const int px_base = blockIdx.x * 64;
    const int frame = blockIdx.y + blockIdx.z * LL;
    const float* s = src + (size_t)frame * CC * HWN;

    #pragma unroll
    for (int it = 0; it < 4; it++) {
        const int li = it * 256 + threadIdx.x;   // [0, 1024): 64 px x 16 ch
        const int px = li & 63;
        const int ch = li >> 6;
        sm[px * PAD + ch] = s[ch * HWN + px_base + px];
    }
    __syncthreads();

    const int px = threadIdx.x >> 2;
    const int cq = threadIdx.x & 3;
    float4 v;
    v.x = sm[px * PAD + cq * 4 + 0];
    v.y = sm[px * PAD + cq * 4 + 1];
    v.z = sm[px * PAD + cq * 4 + 2];
    v.w = sm[px * PAD + cq * 4 + 3];
    dst[(size_t)frame * HWN * 4 + (px_base + px) * 4 + cq] = v;
}

__global__ __launch_bounds__(256) void transpose_flow_kernel(
    const float* __restrict__ src, float2* __restrict__ dst)
{
    const int px = blockIdx.x * blockDim.x + threadIdx.x;
    const int frame = blockIdx.y + blockIdx.z * LL;
    const float* s = src + (size_t)frame * 2 * HWN;
    float2 v;
    v.x = s[px];
    v.y = s[HWN + px];
    dst[(size_t)frame * HWN + px] = v;
}

// ---------------- scan step (NHWC, parity-indirected, 2 px/thread) ----------------
// UNCHANGED from R8 (proven 166us): 4 lanes/pixel, lane-distributed flow taps.

template <int K, int STEP>
__global__ __launch_bounds__(256, 5) void pscan_step(
    float2* flw0, float2* flw1, float4* img0, float4* img1)
{
    const int t   = blockIdx.y + STEP;          // only frames t >= STEP launched
    const int bz  = blockIdx.z;
    const int tid = threadIdx.x;
    const int cq  = tid & 3;
    const int px0 = blockIdx.x * 128 + (tid >> 2);
    const int px1 = px0 + 64;

    const int frame = bz * LL + t;
    const int prevf = frame - STEP;

    const int pc = parity_at(t, K);
    const int pp = parity_at(t - STEP, K);

    const float2* fcur  = (pc ? flw1 : flw0) + (size_t)frame * HWN;
    const float4* icur  = (pc ? img1 : img0) + (size_t)frame * (HWN * 4);
    const float2* fprev = (pp ? flw1 : flw0) + (size_t)prevf * HWN;
    const float4* iprev = (pp ? img1 : img0) + (size_t)prevf * (HWN * 4);
    float2*       fdst  = (pc ? flw0 : flw1) + (size_t)frame * HWN;
    float4*       idst  = (pc ? img0 : img1) + (size_t)frame * (HWN * 4);

    const float2 fc0 = __ldg(&fcur[px0]);
    const float2 fc1 = __ldg(&fcur[px1]);
    const Taps tp0 = make_taps(px0 % WW, px0 / WW, fc0.x, fc0.y);
    const Taps tp1 = make_taps(px1 % WW, px1 / WW, fc1.x, fc1.y);

    // lane-distributed flow tap loads (all 4 lanes of a quad issue one tap each)
    const float2 qf = __ldg(&fprev[tap_sel(tp0, cq)]);
    const float2 rf = __ldg(&fprev[tap_sel(tp1, cq)]);

    // batch all independent image loads for MLP
    const float4 a00 = __ldg(&iprev[tp0.i00 * 4 + cq]);
    const float4 a01 = __ldg(&iprev[tp0.i01 * 4 + cq]);
    const float4 a10 = __ldg(&iprev[tp0.i10 * 4 + cq]);
    const float4 a11 = __ldg(&iprev[tp0.i11 * 4 + cq]);
    const float4 e00 = __ldg(&iprev[tp1.i00 * 4 + cq]);
    const float4 e01 = __ldg(&iprev[tp1.i01 * 4 + cq]);
    const float4 e10 = __ldg(&iprev[tp1.i10 * 4 + cq]);
    const float4 e11 = __ldg(&iprev[tp1.i11 * 4 + cq]);
    const float4 c0  = __ldg(&icur[px0 * 4 + cq]);
    const float4 c1  = __ldg(&icur[px1 * 4 + cq]);

    // shuffle flow taps to quad leader (bits only; arithmetic unchanged)
    const unsigned FULL = 0xffffffffu;
    const float q00x = qf.x,                          q00y = qf.y;
    const float q01x = __shfl_down_sync(FULL, qf.x, 1), q01y = __shfl_down_sync(FULL, qf.y, 1);
    const float q10x = __shfl_down_sync(FULL, qf.x, 2), q10y = __shfl_down_sync(FULL, qf.y, 2);
    const float q11x = __shfl_down_sync(FULL, qf.x, 3), q11y = __shfl_down_sync(FULL, qf.y, 3);
    const float r00x = rf.x,                          r00y = rf.y;
    const float r01x = __shfl_down_sync(FULL, rf.x, 1), r01y = __shfl_down_sync(FULL, rf.y, 1);
    const float r10x = __shfl_down_sync(FULL, rf.x, 2), r10y = __shfl_down_sync(FULL, rf.y, 2);
    const float r11x = __shfl_down_sync(FULL, rf.x, 3), r11y = __shfl_down_sync(FULL, rf.y, 3);

    float4 o0;
    o0.x = __fadd_rn(c0.x, wsum(tp0.w00, a00.x, tp0.w01, a01.x, tp0.w10, a10.x, tp0.w11, a11.x));
    o0.y = __fadd_rn(c0.y, wsum(tp0.w00, a00.y, tp0.w01, a01.y, tp0.w10, a10.y, tp0.w11, a11.y));
    o0.z = __fadd_rn(c0.z, wsum(tp0.w00, a00.z, tp0.w01, a01.z, tp0.w10, a10.z, tp0.w11, a11.z));
    o0.w = __fadd_rn(c0.w, wsum(tp0.w00, a00.w, tp0.w01, a01.w, tp0.w10, a10.w, tp0.w11, a11.w));
    idst[px0 * 4 + cq] = o0;

    float4 o1;
    o1.x = __fadd_rn(c1.x, wsum(tp1.w00, e00.x, tp1.w01, e01.x, tp1.w10, e10.x, tp1.w11, e11.x));
    o1.y = __fadd_rn(c1.y, wsum(tp1.w00, e00.y, tp1.w01, e01.y, tp1.w10, e10.y, tp1.w11, e11.y));
    o1.z = __fadd_rn(c1.z, wsum(tp1.w00, e00.z, tp1.w01, e01.z, tp1.w10, e10.z, tp1.w11, e11.z));
    o1.w = __fadd_rn(c1.w, wsum(tp1.w00, e00.w, tp1.w01, e01.w, tp1.w10, e10.w, tp1.w11, e11.w));
    idst[px1 * 4 + cq] = o1;

    if (cq == 0) {
        float2 of0, of1;
        of0.x = __fadd_rn(fc0.x, wsum(tp0.w00, q00x, tp0.w01, q01x, tp0.w10, q10x, tp0.w11, q11x));
        of0.y = __fadd_rn(fc0.y, wsum(tp0.w00, q00y, tp0.w01, q01y, tp0.w10, q10y, tp0.w11, q11y));
        of1.x = __fadd_rn(fc1.x, wsum(tp1.w00, r00x, tp1.w01, r01x, tp1.w10, r10x, tp1.w11, r11x));
        of1.y = __fadd_rn(fc1.y, wsum(tp1.w00, r00y, tp1.w01, r01y, tp1.w10, r10y, tp1.w11, r11y));
        fdst[px0] = of0;
        fdst[px1] = of1;
    }
}

// final level (K=4, STEP=16): compute in NHWC, smem-stage, coalesced NCHW writeback.
__global__ __launch_bounds__(256, 5) void pscan_final(
    float2* flw0, float2* flw1, float4* img0, float4* img1,
    float* __restrict__ out)
{
    __shared__ float sm[128 * PAD];

    const int t   = blockIdx.y;
    const int bz  = blockIdx.z;
    const int tid = threadIdx.x;
    const int cq  = tid & 3;
    const int px_base = blockIdx.x * 128;
    const int p0l = tid >> 2;            // local px 0..63
    const int p1l = p0l + 64;            // local px 64..127
    const int px0 = px_base + p0l;
    const int px1 = px_base + p1l;

    const int frame = bz * LL + t;
    const int pc = parity_at(t, 4);
    const float4* icur = (pc ? img1 : img0) + (size_t)frame * (HWN * 4);

    float4 o0, o1;

    if (t < 16) {
        // prefix frames: live value passes through
        o0 = __ldg(&icur[px0 * 4 + cq]);
        o1 = __ldg(&icur[px1 * 4 + cq]);
    } else {
        const int prevf = frame - 16;
        const int pp = parity_at(t - 16, 4);
        const float2* fcur  = (pc ? flw1 : flw0) + (size_t)frame * HWN;
        const float4* iprev = (pp ? img1 : img0) + (size_t)prevf * (HWN * 4);

        const float2 fc0 = __ldg(&fcur[px0]);
        const float2 fc1 = __ldg(&fcur[px1]);
        const Taps tp0 = make_taps(px0 % WW, px0 / WW, fc0.x, fc0.y);
        const Taps tp1 = make_taps(px1 % WW, px1 / WW, fc1.x, fc1.y);

        const float4 a00 = __ldg(&iprev[tp0.i00 * 4 + cq]);
        const float4 a01 = __ldg(&iprev[tp0.i01 * 4 + cq]);
        const float4 a10 = __ldg(&iprev[tp0.i10 * 4 + cq]);
        const float4 a11 = __ldg(&iprev[tp0.i11 * 4 + cq]);
        const float4 e00 = __ldg(&iprev[tp1.i00 * 4 + cq]);
        const float4 e01 = __ldg(&iprev[tp1.i01 * 4 + cq]);
        const float4 e10 = __ldg(&iprev[tp1.i10 * 4 + cq]);
        const float4 e11 = __ldg(&iprev[tp1.i11 * 4 + cq]);
        const float4 c0  = __ldg(&icur[px0 * 4 + cq]);
        const float4 c1  = __ldg(&icur[px1 * 4 + cq]);

        o0.x = __fadd_rn(c0.x, wsum(tp0.w00, a00.x, tp0.w01, a01.x, tp0.w10, a10.x, tp0.w11, a11.x));
        o0.y = __fadd_rn(c0.y, wsum(tp0.w00, a00.y, tp0.w01, a01.y, tp0.w10, a10.y, tp0.w11, a11.y));
        o0.z = __fadd_rn(c0.z, wsum(tp0.w00, a00.z, tp0.w01, a01.z, tp0.w10, a10.z, tp0.w11, a11.z));
        o0.w = __fadd_rn(c0.w, wsum(tp0.w00, a00.w, tp0.w01, a01.w, tp0.w10, a10.w, tp0.w11, a11.w));
        o1.x = __fadd_rn(c1.x, wsum(tp1.w00, e00.x, tp1.w01, e01.x, tp1.w10, e10.x, tp1.w11, e11.x));
        o1.y = __fadd_rn(c1.y, wsum(tp1.w00, e00.y, tp1.w01, e01.y, tp1.w10, e10.y, tp1.w11, e11.y));
        o1.z = __fadd_rn(c1.z, wsum(tp1.w00, e00.z, tp1.w01, e01.z, tp1.w10, e10.z, tp1.w11, e11.z));
        o1.w = __fadd_rn(c1.w, wsum(tp1.w00, e00.w, tp1.w01, e01.w, tp1.w10, e10.w, tp1.w11, e11.w));
    }

    // stage NHWC results into smem tile [128 px][16 ch] (pad 17)
    sm[p0l * PAD + cq * 4 + 0] = o0.x;
    sm[p0l * PAD + cq * 4 + 1] = o0.y;
    sm[p0l * PAD + cq * 4 + 2] = o0.z;
    sm[p0l * PAD + cq * 4 + 3] = o0.w;
    sm[p1l * PAD + cq * 4 + 0] = o1.x;
    sm[p1l * PAD + cq * 4 + 1] = o1.y;
    sm[p1l * PAD + cq * 4 + 2] = o1.z;
    sm[p1l * PAD + cq * 4 + 3] = o1.w;
    __syncthreads();

    // coalesced NCHW writeback: warp writes 128B runs per channel plane
    float* dimg = out + (size_t)frame * CC * HWN;
    #pragma unroll
    for (int it = 0; it < 8; it++) {
        const int li = it * 256 + tid;       // [0, 2048): 16 ch x 128 px
        const int ch = li >> 7;
        const int px = li & 127;
        dimg[ch * HWN + px_base + px] = sm[px * PAD + ch];
    }
}

extern "C" void kernel_launch(void* const* d_in, const int* in_sizes, int n_in,
                              void* d_out, int out_size)
{
    // Defensive input-order resolution via element counts
    const float* in_flows  = (const float*)d_in[0];  // [B,L,2,H,W]
    const float* in_images = (const float*)d_in[1];  // [B,L,C,H,W]
    if (in_sizes[0] == IMG_ELEMS && in_sizes[1] == FLOW_ELEMS) {
        in_flows  = (const float*)d_in[1];
        in_images = (const float*)d_in[0];
    }
    float* out_images = (float*)d_out;               // [B,L,C,H,W]

    float4 *i0, *i1;
    float2 *f0, *f1;
    cudaGetSymbolAddress((void**)&i0, g_img0);
    cudaGetSymbolAddress((void**)&i1, g_img1);
    cudaGetSymbolAddress((void**)&f0, g_flw0);
    cudaGetSymbolAddress((void**)&f1, g_flw1);

    dim3 block(256);

    // transposes: NCHW -> NHWC / interleaved, into parity-0 buffers
    {
        dim3 gridI(HWN / 64, LL, BB);        // smem-staged, 64 px/block
        transpose_img_kernel<<<gridI, block>>>(in_images, i0);
        dim3 gridF(HWN / 256, LL, BB);
        transpose_flow_kernel<<<gridF, block>>>(in_flows, f0);
    }

    // scan levels; only frames t >= step launched (prefix never copied)
    {
        dim3 g1(HWN / 128, LL - 1, BB);
        pscan_step<0, 1><<<g1, block>>>(f0, f1, i0, i1);
        dim3 g2(HWN / 128, LL - 2, BB);
        pscan_step<1, 2><<<g2, block>>>(f0, f1, i0, i1);
        dim3 g4(HWN / 128, LL - 4, BB);
        pscan_step<2, 4><<<g4, block>>>(f0, f1, i0, i1);
        dim3 g8(HWN / 128, LL - 8, BB);
        pscan_step<3, 8><<<g8, block>>>(f0, f1, i0, i1);
    }

    // final level: parity-resolved read, smem-staged coalesced NCHW output
    {
        dim3 gf(HWN / 128, LL, BB);
        pscan_final<<<gf, block>>>(f0, f1, i0, i1, out_images);
    }
}

// round 11
// speedup vs baseline: 2.9726x; 1.0094x over previous
#include <cuda_runtime.h>
#include <math.h>

// Problem dims (fixed by the reference setup_inputs)
#define BB 4
#define LL 32
#define CC 16
#define HH 192
#define WW 192
#define HWN (HH * WW)                    // 36864
#define FLOW_ELEMS (BB * LL * 2 * HWN)   // 9,437,184
#define IMG_ELEMS  (BB * LL * CC * HWN)  // 75,497,472
#define PAD 17                           // smem row pad (floats) -> conflict-free

// Scratch (allocation-free rule: __device__ globals).
__device__ float4 g_img0[IMG_ELEMS / 4];
__device__ float4 g_img1[IMG_ELEMS / 4];
__device__ float2 g_flw0[FLOW_ELEMS / 2];
__device__ float2 g_flw1[FLOW_ELEMS / 2];

// Exact floor-mod by 2.0, value-identical to jnp.remainder(z, 2.0) in fp32.
__device__ __forceinline__ float floor_mod2(float z) {
    float q = floorf(__fmul_rn(z, 0.5f));
    return __fsub_rn(z, __fmul_rn(2.0f, q));
}

// Buffer (0/1) holding frame t's live value at the START of level k.
__device__ __forceinline__ int parity_at(int t, int k) {
    if (t == 0) return 0;
    int f = 31 - __clz(t);
    int u = min(k, f + 1);
    return u & 1;
}

// Bit-exact coordinate/weight computation (no fma, reference association).
struct Taps {
    int i00, i01, i10, i11;
    float w00, w01, w10, w11;
};
__device__ __forceinline__ Taps make_taps(int x, int y, float f0, float f1) {
    const float C2W = (float)(2.0 / 192.0);
    const float gx = __fsub_rn(__fmul_rn(__fadd_rn((float)x, 0.5f), C2W), 1.0f);
    const float gy = __fsub_rn(__fmul_rn(__fadd_rn((float)y, 0.5f), C2W), 1.0f);

    const float fx_u = __fadd_rn(gx, f0);
    const float fy   = __fadd_rn(gy, f1);
    const float z  = __fadd_rn(fx_u, 1.0f);
    const float fx = __fsub_rn(floor_mod2(z), 1.0f);

    const float ix = __fsub_rn(__fmul_rn(__fmul_rn(__fadd_rn(fx, 1.0f), 0.5f), (float)WW), 0.5f);
    const float iy = __fsub_rn(__fmul_rn(__fmul_rn(__fadd_rn(fy, 1.0f), 0.5f), (float)HH), 0.5f);

    const float x0f = floorf(ix);
    const float y0f = floorf(iy);
    const float wx1 = __fsub_rn(ix, x0f);
    const float wy1 = __fsub_rn(iy, y0f);
    const float wx0 = __fsub_rn(1.0f, wx1);
    const float wy0 = __fsub_rn(1.0f, wy1);

    const int x0 = (int)x0f, y0 = (int)y0f;
    const int x1 = x0 + 1,  y1 = y0 + 1;

    const bool vx0 = (x0 >= 0) & (x0 < WW);
    const bool vx1 = (x1 >= 0) & (x1 < WW);
    const bool vy0 = (y0 >= 0) & (y0 < HH);
    const bool vy1 = (y1 >= 0) & (y1 < HH);

    const int xc0 = min(max(x0, 0), WW - 1);
    const int xc1 = min(max(x1, 0), WW - 1);
    const int yc0 = min(max(y0, 0), HH - 1);
    const int yc1 = min(max(y1, 0), HH - 1);

    Taps tp;
    tp.w00 = __fmul_rn(__fmul_rn(wy0, wx0), (vy0 & vx0) ? 1.0f : 0.0f);
    tp.w01 = __fmul_rn(__fmul_rn(wy0, wx1), (vy0 & vx1) ? 1.0f : 0.0f);
    tp.w10 = __fmul_rn(__fmul_rn(wy1, wx0), (vy1 & vx0) ? 1.0f : 0.0f);
    tp.w11 = __fmul_rn(__fmul_rn(wy1, wx1), (vy1 & vx1) ? 1.0f : 0.0f);
    tp.i00 = yc0 * WW + xc0;
    tp.i01 = yc0 * WW + xc1;
    tp.i10 = yc1 * WW + xc0;
    tp.i11 = yc1 * WW + xc1;
    return tp;
}

__device__ __forceinline__ int tap_sel(const Taps& tp, int j) {
    return j == 0 ? tp.i00 : (j == 1 ? tp.i01 : (j == 2 ? tp.i10 : tp.i11));
}

// Exact left-assoc weighted sum: ((w00*a + w01*b) + w10*c) + w11*d
__device__ __forceinline__ float wsum(float w00, float a, float w01, float b,
                                      float w10, float c, float w11, float d) {
    return __fadd_rn(
             __fadd_rn(
               __fadd_rn(__fmul_rn(w00, a), __fmul_rn(w01, b)),
               __fmul_rn(w10, c)),
             __fmul_rn(w11, d));
}

__device__ __forceinline__ float4 shfl_xor4_f4(float4 v) {
    const unsigned FULL = 0xffffffffu;
    float4 r;
    r.x = __shfl_xor_sync(FULL, v.x, 4);
    r.y = __shfl_xor_sync(FULL, v.y, 4);
    r.z = __shfl_xor_sync(FULL, v.z, 4);
    r.w = __shfl_xor_sync(FULL, v.w, 4);
    return r;
}

// ---------------- transpose kernels (inputs -> parity-0 buffers) ----------------

__global__ __launch_bounds__(256) void transpose_img_kernel(
    const float* __restrict__ src, float4* __restrict__ dst)
{
    __shared__ float sm[64 * PAD];
    const int px_base = blockIdx.x * 64;
    const int frame = blockIdx.y + blockIdx.z * LL;
    const float* s = src + (size_t)frame * CC * HWN;

    #pragma unroll
    for (int it = 0; it < 4; it++) {
        const int li = it * 256 + threadIdx.x;
        const int px = li & 63;
        const int ch = li >> 6;
        sm[px * PAD + ch] = s[ch * HWN + px_base + px];
    }
    __syncthreads();

    const int px = threadIdx.x >> 2;
    const int cq = threadIdx.x & 3;
    float4 v;
    v.x = sm[px * PAD + cq * 4 + 0];
    v.y = sm[px * PAD + cq * 4 + 1];
    v.z = sm[px * PAD + cq * 4 + 2];
    v.w = sm[px * PAD + cq * 4 + 3];
    dst[(size_t)frame * HWN * 4 + (px_base + px) * 4 + cq] = v;
}

__global__ __launch_bounds__(256) void transpose_flow_kernel(
    const float* __restrict__ src, float2* __restrict__ dst)
{
    const int px = blockIdx.x * blockDim.x + threadIdx.x;
    const int frame = blockIdx.y + blockIdx.z * LL;
    const float* s = src + (size_t)frame * 2 * HWN;
    float2 v;
    v.x = s[px];
    v.y = s[HWN + px];
    dst[(size_t)frame * HWN + px] = v;
}

// ---------------- scan step: 8 lanes per pixel-pair, row-pair merged taps -------
// Group of 8 lanes handles 2 pixels (A = base+k, B = base+4+k). Lane: half = s>>2
// (0 -> owns A / loads left taps, 1 -> owns B / loads right taps), q = s&3 (quad).
// Image tap loads are issued so each group's 8 lanes cover one pixel's x-adjacent
// (left,right) 64B chunks -> contiguous 128B per group. Values/indices exchanged
// with shfl_xor(4); all arithmetic done per-lane on its OWN pixel with the exact
// left-associative, non-fma chain (bit-exactness preserved).

template <int K, int STEP>
__global__ __launch_bounds__(256, 5) void pscan_step(
    float2* flw0, float2* flw1, float4* img0, float4* img1)
{
    const unsigned FULL = 0xffffffffu;
    const int t   = blockIdx.y + STEP;          // only frames t >= STEP launched
    const int bz  = blockIdx.z;
    const int tid = threadIdx.x;
    const int s    = tid & 7;
    const int half = s >> 2;
    const int q    = s & 3;
    const int k    = (tid >> 3) & 3;            // group within warp
    const int wbase = blockIdx.x * 128 + (tid >> 5) * 8;  // slot-0 warp pixel base

    const int frame = bz * LL + t;
    const int prevf = frame - STEP;
    const int pc = parity_at(t, K);
    const int pp = parity_at(t - STEP, K);

    const float2* fcur  = (pc ? flw1 : flw0) + (size_t)frame * HWN;
    const float4* icur  = (pc ? img1 : img0) + (size_t)frame * (HWN * 4);
    const float2* fprev = (pp ? flw1 : flw0) + (size_t)prevf * HWN;
    const float4* iprev = (pp ? img1 : img0) + (size_t)prevf * (HWN * 4);
    float2*       fdst  = (pc ? flw0 : flw1) + (size_t)frame * HWN;
    float4*       idst  = (pc ? img0 : img1) + (size_t)frame * (HWN * 4);

    #pragma unroll
    for (int slot = 0; slot < 2; slot++) {
        const int base = wbase + slot * 64;
        const int pxO  = base + half * 4 + k;   // owned pixel (A for half=0, B for half=1)

        const float2 fcO = __ldg(&fcur[pxO]);
        const Taps tpO = make_taps(pxO % WW, pxO / WW, fcO.x, fcO.y);

        // index exchange: send what partner needs for its cross-pixel row loads
        const int idxs0 = __shfl_xor_sync(FULL, half ? tpO.i00 : tpO.i01, 4);
        const int idxs1 = __shfl_xor_sync(FULL, half ? tpO.i10 : tpO.i11, 4);
        // half=0 received: i00B, i10B   half=1 received: i01A, i11A

        // row-pair image tap loads (each group instruction = contiguous 128B)
        const float4 rowA0 = __ldg(&iprev[(half ? idxs0   : tpO.i00) * 4 + q]);
        const float4 rowA1 = __ldg(&iprev[(half ? idxs1   : tpO.i10) * 4 + q]);
        const float4 rowB0 = __ldg(&iprev[(half ? tpO.i01 : idxs0  ) * 4 + q]);
        const float4 rowB1 = __ldg(&iprev[(half ? tpO.i11 : idxs1  ) * 4 + q]);
        const float4 c     = __ldg(&icur[pxO * 4 + q]);
        // flow tap: lane q loads its own pixel's tap q
        const float2 ftap  = __ldg(&fprev[tap_sel(tpO, q)]);

        // value exchange: send the half the partner's output needs
        float4 sel0, sel1;
        sel0 = half ? rowA0 : rowB0;    // half=1 sends t01(A); half=0 sends t00(B)
        sel1 = half ? rowA1 : rowB1;
        const float4 opp0 = shfl_xor4_f4(sel0);  // half=0 <- t01(A); half=1 <- t00(B)
        const float4 opp1 = shfl_xor4_f4(sel1);  // half=0 <- t11(A); half=1 <- t10(B)

        const float4 t00 = half ? opp0  : rowA0;
        const float4 t01 = half ? rowB0 : opp0;
        const float4 t10 = half ? opp1  : rowA1;
        const float4 t11 = half ? rowB1 : opp1;

        float4 o;
        o.x = __fadd_rn(c.x, wsum(tpO.w00, t00.x, tpO.w01, t01.x, tpO.w10, t10.x, tpO.w11, t11.x));
        o.y = __fadd_rn(c.y, wsum(tpO.w00, t00.y, tpO.w01, t01.y, tpO.w10, t10.y, tpO.w11, t11.y));
        o.z = __fadd_rn(c.z, wsum(tpO.w00, t00.z, tpO.w01, t01.z, tpO.w10, t10.z, tpO.w11, t11.z));
        o.w = __fadd_rn(c.w, wsum(tpO.w00, t00.w, tpO.w01, t01.w, tpO.w10, t10.w, tpO.w11, t11.w));
        idst[pxO * 4 + q] = o;

        // flow output on lane q==0 of each half (own pixel's 4 taps from lanes q..q+3)
        const float f01x = __shfl_down_sync(FULL, ftap.x, 1);
        const float f01y = __shfl_down_sync(FULL, ftap.y, 1);
        const float f10x = __shfl_down_sync(FULL, ftap.x, 2);
        const float f10y = __shfl_down_sync(FULL, ftap.y, 2);
        const float f11x = __shfl_down_sync(FULL, ftap.x, 3);
        const float f11y = __shfl_down_sync(FULL, ftap.y, 3);
        if (q == 0) {
            float2 of;
            of.x = __fadd_rn(fcO.x, wsum(tpO.w00, ftap.x, tpO.w01, f01x, tpO.w10, f10x, tpO.w11, f11x));
            of.y = __fadd_rn(fcO.y, wsum(tpO.w00, ftap.y, tpO.w01, f01y, tpO.w10, f10y, tpO.w11, f11y));
            fdst[pxO] = of;
        }
    }
}

// final level (K=4, STEP=16): compute in NHWC, smem-stage, coalesced NCHW writeback.
__global__ __launch_bounds__(256, 5) void pscan_final(
    float2* flw0, float2* flw1, float4* img0, float4* img1,
    float* __restrict__ out)
{
    __shared__ float sm[128 * PAD];

    const int t   = blockIdx.y;
    const int bz  = blockIdx.z;
    const int tid = threadIdx.x;
    const int cq  = tid & 3;
    const int px_base = blockIdx.x * 128;
    const int p0l = tid >> 2;
    const int p1l = p0l + 64;
    const int px0 = px_base + p0l;
    const int px1 = px_base + p1l;

    const int frame = bz * LL + t;
    const int pc = parity_at(t, 4);
    const float4* icur = (pc ? img1 : img0) + (size_t)frame * (HWN * 4);

    float4 o0, o1;

    if (t < 16) {
        o0 = __ldg(&icur[px0 * 4 + cq]);
        o1 = __ldg(&icur[px1 * 4 + cq]);
    } else {
        const int prevf = frame - 16;
        const int pp = parity_at(t - 16, 4);
        const float2* fcur  = (pc ? flw1 : flw0) + (size_t)frame * HWN;
        const float4* iprev = (pp ? img1 : img0) + (size_t)prevf * (HWN * 4);

        const float2 fc0 = __ldg(&fcur[px0]);
        const float2 fc1 = __ldg(&fcur[px1]);
        const Taps tp0 = make_taps(px0 % WW, px0 / WW, fc0.x, fc0.y);
        const Taps tp1 = make_taps(px1 % WW, px1 / WW, fc1.x, fc1.y);

        const float4 a00 = __ldg(&iprev[tp0.i00 * 4 + cq]);
        const float4 a01 = __ldg(&iprev[tp0.i01 * 4 + cq]);
        const float4 a10 = __ldg(&iprev[tp0.i10 * 4 + cq]);
        const float4 a11 = __ldg(&iprev[tp0.i11 * 4 + cq]);
        const float4 e00 = __ldg(&iprev[tp1.i00 * 4 + cq]);
        const float4 e01 = __ldg(&iprev[tp1.i01 * 4 + cq]);
        const float4 e10 = __ldg(&iprev[tp1.i10 * 4 + cq]);
        const float4 e11 = __ldg(&iprev[tp1.i11 * 4 + cq]);
        const float4 c0  = __ldg(&icur[px0 * 4 + cq]);
        const float4 c1  = __ldg(&icur[px1 * 4 + cq]);

        o0.x = __fadd_rn(c0.x, wsum(tp0.w00, a00.x, tp0.w01, a01.x, tp0.w10, a10.x, tp0.w11, a11.x));
        o0.y = __fadd_rn(c0.y, wsum(tp0.w00, a00.y, tp0.w01, a01.y, tp0.w10, a10.y, tp0.w11, a11.y));
        o0.z = __fadd_rn(c0.z, wsum(tp0.w00, a00.z, tp0.w01, a01.z, tp0.w10, a10.z, tp0.w11, a11.z));
        o0.w = __fadd_rn(c0.w, wsum(tp0.w00, a00.w, tp0.w01, a01.w, tp0.w10, a10.w, tp0.w11, a11.w));
        o1.x = __fadd_rn(c1.x, wsum(tp1.w00, e00.x, tp1.w01, e01.x, tp1.w10, e10.x, tp1.w11, e11.x));
        o1.y = __fadd_rn(c1.y, wsum(tp1.w00, e00.y, tp1.w01, e01.y, tp1.w10, e10.y, tp1.w11, e11.y));
        o1.z = __fadd_rn(c1.z, wsum(tp1.w00, e00.z, tp1.w01, e01.z, tp1.w10, e10.z, tp1.w11, e11.z));
        o1.w = __fadd_rn(c1.w, wsum(tp1.w00, e00.w, tp1.w01, e01.w, tp1.w10, e10.w, tp1.w11, e11.w));
    }

    sm[p0l * PAD + cq * 4 + 0] = o0.x;
    sm[p0l * PAD + cq * 4 + 1] = o0.y;
    sm[p0l * PAD + cq * 4 + 2] = o0.z;
    sm[p0l * PAD + cq * 4 + 3] = o0.w;
    sm[p1l * PAD + cq * 4 + 0] = o1.x;
    sm[p1l * PAD + cq * 4 + 1] = o1.y;
    sm[p1l * PAD + cq * 4 + 2] = o1.z;
    sm[p1l * PAD + cq * 4 + 3] = o1.w;
    __syncthreads();

    float* dimg = out + (size_t)frame * CC * HWN;
    #pragma unroll
    for (int it = 0; it < 8; it++) {
        const int li = it * 256 + tid;
        const int ch = li >> 7;
        const int px = li & 127;
        dimg[ch * HWN + px_base + px] = sm[px * PAD + ch];
    }
}

extern "C" void kernel_launch(void* const* d_in, const int* in_sizes, int n_in,
                              void* d_out, int out_size)
{
    const float* in_flows  = (const float*)d_in[0];  // [B,L,2,H,W]
    const float* in_images = (const float*)d_in[1];  // [B,L,C,H,W]
    if (in_sizes[0] == IMG_ELEMS && in_sizes[1] == FLOW_ELEMS) {
        in_flows  = (const float*)d_in[1];
        in_images = (const float*)d_in[0];
    }
    float* out_images = (float*)d_out;               // [B,L,C,H,W]

    float4 *i0, *i1;
    float2 *f0, *f1;
    cudaGetSymbolAddress((void**)&i0, g_img0);
    cudaGetSymbolAddress((void**)&i1, g_img1);
    cudaGetSymbolAddress((void**)&f0, g_flw0);
    cudaGetSymbolAddress((void**)&f1, g_flw1);

    dim3 block(256);

    {
        dim3 gridI(HWN / 64, LL, BB);
        transpose_img_kernel<<<gridI, block>>>(in_images, i0);
        dim3 gridF(HWN / 256, LL, BB);
        transpose_flow_kernel<<<gridF, block>>>(in_flows, f0);
    }

    {
        dim3 g1(HWN / 128, LL - 1, BB);
        pscan_step<0, 1><<<g1, block>>>(f0, f1, i0, i1);
        dim3 g2(HWN / 128, LL - 2, BB);
        pscan_step<1, 2><<<g2, block>>>(f0, f1, i0, i1);
        dim3 g4(HWN / 128, LL - 4, BB);
        pscan_step<2, 4><<<g4, block>>>(f0, f1, i0, i1);
        dim3 g8(HWN / 128, LL - 8, BB);
        pscan_step<3, 8><<<g8, block>>>(f0, f1, i0, i1);
    }

    {
        dim3 gf(HWN / 128, LL, BB);
        pscan_final<<<gf, block>>>(f0, f1, i0, i1, out_images);
    }
}